// round 1
// baseline (speedup 1.0000x reference)
#include <cuda_runtime.h>
#include <math.h>

// Problem dims (fixed for this dataset entry)
#define B_   2
#define T_   4096
#define D_   2048
#define H_   32
#define DK   64
#define BS_  128            // query block size == window
#define NB   (T_ / BS_)     // 32
#define M_   (B_ * T_)      // 8192

// ---------------------------------------------------------------------------
// Scratch (device globals: allocation inside kernel_launch is forbidden)
// ---------------------------------------------------------------------------
__device__ float g_Q [(size_t)M_ * D_];
__device__ float g_K [(size_t)M_ * D_];
__device__ float g_V [(size_t)M_ * D_];
__device__ float g_AO[(size_t)M_ * D_];

// ---------------------------------------------------------------------------
// SGEMM (NT): C[m][n] = sum_k A[m][k] * B[n][k]
// A: [M,K] row-major, B: [N,K] row-major (both K-contiguous), C: [M,N]
// 128x128 block tile, BK=16, 256 threads, 8x8 per-thread microtile.
// ---------------------------------------------------------------------------
#define BM 128
#define BN 128
#define BK 16

__global__ __launch_bounds__(256, 2) void sgemm_nt(
    const float* __restrict__ A, const float* __restrict__ Bw,
    float* __restrict__ C, int M, int N, int K)
{
    __shared__ __align__(16) float As[BK][BM + 4];
    __shared__ __align__(16) float Bs[BK][BN + 4];

    const int tid = threadIdx.x;
    const int bm  = blockIdx.y * BM;
    const int bn  = blockIdx.x * BN;
    const int tx  = tid & 15;
    const int ty  = tid >> 4;
    const int m_off = ty * 8;
    const int n_off = tx * 8;

    // global-load mapping: 64 rows x 16 k-cols per half, 2 halves
    const int lrow = tid >> 2;          // 0..63
    const int lcol = (tid & 3) << 2;    // 0,4,8,12

    const float* Ap = A  + (size_t)(bm + lrow) * K + lcol;
    const float* Bp = Bw + (size_t)(bn + lrow) * K + lcol;

    float acc[8][8];
#pragma unroll
    for (int i = 0; i < 8; ++i)
#pragma unroll
        for (int j = 0; j < 8; ++j) acc[i][j] = 0.0f;

    for (int k0 = 0; k0 < K; k0 += BK) {
        float4 a0 = *(const float4*)(Ap + k0);
        float4 a1 = *(const float4*)(Ap + k0 + (size_t)64 * K);
        float4 b0 = *(const float4*)(Bp + k0);
        float4 b1 = *(const float4*)(Bp + k0 + (size_t)64 * K);

        As[lcol + 0][lrow]      = a0.x;
        As[lcol + 1][lrow]      = a0.y;
        As[lcol + 2][lrow]      = a0.z;
        As[lcol + 3][lrow]      = a0.w;
        As[lcol + 0][lrow + 64] = a1.x;
        As[lcol + 1][lrow + 64] = a1.y;
        As[lcol + 2][lrow + 64] = a1.z;
        As[lcol + 3][lrow + 64] = a1.w;

        Bs[lcol + 0][lrow]      = b0.x;
        Bs[lcol + 1][lrow]      = b0.y;
        Bs[lcol + 2][lrow]      = b0.z;
        Bs[lcol + 3][lrow]      = b0.w;
        Bs[lcol + 0][lrow + 64] = b1.x;
        Bs[lcol + 1][lrow + 64] = b1.y;
        Bs[lcol + 2][lrow + 64] = b1.z;
        Bs[lcol + 3][lrow + 64] = b1.w;

        __syncthreads();

#pragma unroll
        for (int kk = 0; kk < BK; ++kk) {
            float ar[8], br[8];
            *(float4*)(ar)     = *(const float4*)&As[kk][m_off];
            *(float4*)(ar + 4) = *(const float4*)&As[kk][m_off + 4];
            *(float4*)(br)     = *(const float4*)&Bs[kk][n_off];
            *(float4*)(br + 4) = *(const float4*)&Bs[kk][n_off + 4];
#pragma unroll
            for (int i = 0; i < 8; ++i)
#pragma unroll
                for (int j = 0; j < 8; ++j)
                    acc[i][j] += ar[i] * br[j];
        }
        __syncthreads();
    }

#pragma unroll
    for (int i = 0; i < 8; ++i) {
        float* cp = C + (size_t)(bm + m_off + i) * N + bn + n_off;
        *(float4*)(cp)     = make_float4(acc[i][0], acc[i][1], acc[i][2], acc[i][3]);
        *(float4*)(cp + 4) = make_float4(acc[i][4], acc[i][5], acc[i][6], acc[i][7]);
    }
}

// ---------------------------------------------------------------------------
// Sliding-window attention.
// grid = (NB, H, B), block = 128 threads; thread r owns query row (i*128 + r).
// Key window for q-block i: global keys [(i-1)*128, (i+1)*128) = 256 candidates
// (c in [0,256)). Row r valid keys: r <= c <= r+128, and c >= 128 if i == 0.
// Online softmax; q and o accumulator live in registers (dk = 64).
// K/V streamed through shared memory in 64-key chunks.
// ---------------------------------------------------------------------------
__global__ __launch_bounds__(128) void swa_kernel(
    const float* __restrict__ Q, const float* __restrict__ Kt,
    const float* __restrict__ Vt, float* __restrict__ O)
{
    const int i = blockIdx.x;     // query block
    const int h = blockIdx.y;     // head
    const int b = blockIdx.z;     // batch
    const int r = threadIdx.x;    // query row in block (0..127)

    __shared__ __align__(16) float Kc[64][64];
    __shared__ __align__(16) float Vc[64][64];

    const float scale = 0.125f;   // 1/sqrt(64)

    float q[DK];
    const size_t rowoff = ((size_t)b * T_ + (size_t)i * BS_ + r) * D_ + (size_t)h * DK;
#pragma unroll
    for (int d = 0; d < DK; d += 4) {
        float4 t = *(const float4*)(Q + rowoff + d);
        q[d] = t.x; q[d + 1] = t.y; q[d + 2] = t.z; q[d + 3] = t.w;
    }

    float o[DK];
#pragma unroll
    for (int d = 0; d < DK; ++d) o[d] = 0.0f;
    float mval = -INFINITY;
    float l = 0.0f;

    const int base_t  = (i - 1) * BS_;
    const int cmin    = (i == 0) ? 128 : r;   // max(r, i==0 ? 128 : 0); r < 128
    const int cmax    = r + 128;
    const int c_start = (i == 0) ? 128 : 0;   // whole first half invalid at i==0

    const int sub = r >> 4;          // 0..7  (row-in-group for loads)
    const int d4  = (r & 15) * 4;    // float4 column

    for (int c0 = c_start; c0 < 256; c0 += 64) {
        __syncthreads();
        // cooperative chunk load: 64 keys x 64 dims (K and V)
#pragma unroll
        for (int it = 0; it < 8; ++it) {
            int j  = it * 8 + sub;
            int tk = base_t + c0 + j;      // >= 0 by construction of c_start
            size_t off = ((size_t)b * T_ + tk) * D_ + (size_t)h * DK + d4;
            float4 kv = *(const float4*)(Kt + off);
            float4 vv = *(const float4*)(Vt + off);
            *(float4*)&Kc[j][d4] = kv;
            *(float4*)&Vc[j][d4] = vv;
        }
        __syncthreads();

        for (int j = 0; j < 64; ++j) {
            const int c = c0 + j;
            if (c < cmin || c > cmax) continue;

            float s = 0.0f;
#pragma unroll
            for (int d = 0; d < DK; d += 4) {
                float4 k4 = *(const float4*)&Kc[j][d];
                s += q[d] * k4.x + q[d + 1] * k4.y + q[d + 2] * k4.z + q[d + 3] * k4.w;
            }
            s *= scale;

            if (s > mval) {                 // rare (~log2(256) times per row)
                float corr = __expf(mval - s);   // exp(-inf) = 0 on first hit
                l *= corr;
#pragma unroll
                for (int d = 0; d < DK; ++d) o[d] *= corr;
                mval = s;
            }
            float p = __expf(s - mval);
            l += p;
#pragma unroll
            for (int d = 0; d < DK; d += 4) {
                float4 v4 = *(const float4*)&Vc[j][d];
                o[d]     += p * v4.x;
                o[d + 1] += p * v4.y;
                o[d + 2] += p * v4.z;
                o[d + 3] += p * v4.w;
            }
        }
    }

    const float inv = 1.0f / l;
    float* op = O + rowoff;
#pragma unroll
    for (int d = 0; d < DK; d += 4) {
        *(float4*)(op + d) = make_float4(o[d] * inv, o[d + 1] * inv,
                                         o[d + 2] * inv, o[d + 3] * inv);
    }
}

// ---------------------------------------------------------------------------
// Launch: x->Q,K,V (3 GEMMs), attention, attnO->out (1 GEMM)
// ---------------------------------------------------------------------------
extern "C" void kernel_launch(void* const* d_in, const int* in_sizes, int n_in,
                              void* d_out, int out_size)
{
    const float* x  = (const float*)d_in[0];
    const float* Wq = (const float*)d_in[1];
    const float* Wk = (const float*)d_in[2];
    const float* Wv = (const float*)d_in[3];
    const float* Wo = (const float*)d_in[4];
    float* out = (float*)d_out;

    float *qp, *kp, *vp, *aop;
    cudaGetSymbolAddress((void**)&qp,  g_Q);
    cudaGetSymbolAddress((void**)&kp,  g_K);
    cudaGetSymbolAddress((void**)&vp,  g_V);
    cudaGetSymbolAddress((void**)&aop, g_AO);

    dim3 gg(D_ / BN, M_ / BM);   // (16, 64)
    sgemm_nt<<<gg, 256>>>(x,   Wq, qp,  M_, D_, D_);
    sgemm_nt<<<gg, 256>>>(x,   Wk, kp,  M_, D_, D_);
    sgemm_nt<<<gg, 256>>>(x,   Wv, vp,  M_, D_, D_);

    dim3 ga(NB, H_, B_);         // (32, 32, 2)
    swa_kernel<<<ga, 128>>>(qp, kp, vp, aop);

    sgemm_nt<<<gg, 256>>>(aop, Wo, out, M_, D_, D_);
}

// round 3
// speedup vs baseline: 1.9728x; 1.9728x over previous
#include <cuda_runtime.h>
#include <cuda_bf16.h>
#include <math.h>
#include <stdint.h>

// Problem dims (fixed)
#define B_   2
#define T_   4096
#define D_   2048
#define H_   32
#define DK   64
#define BS_  128
#define NB   (T_ / BS_)     // 32
#define M_   (B_ * T_)      // 8192

// ---------------------------------------------------------------------------
// Scratch device globals
// ---------------------------------------------------------------------------
__device__ float g_Q [(size_t)M_ * D_];
__device__ float g_K [(size_t)M_ * D_];
__device__ float g_V [(size_t)M_ * D_];
__device__ float g_AO[(size_t)M_ * D_];

__device__ __nv_bfloat16 g_xhi[(size_t)M_ * D_];
__device__ __nv_bfloat16 g_xlo[(size_t)M_ * D_];
__device__ __nv_bfloat16 g_aohi[(size_t)M_ * D_];
__device__ __nv_bfloat16 g_aolo[(size_t)M_ * D_];
__device__ __nv_bfloat16 g_whi[4][(size_t)D_ * D_];
__device__ __nv_bfloat16 g_wlo[4][(size_t)D_ * D_];

// ---------------------------------------------------------------------------
// helpers
// ---------------------------------------------------------------------------
__device__ __forceinline__ uint32_t smem_to_u32(const void* p) {
    uint32_t a;
    asm("{ .reg .u64 t; cvta.to.shared.u64 t, %1; cvt.u32.u64 %0, t; }" : "=r"(a) : "l"(p));
    return a;
}
__device__ __forceinline__ void cp16(uint32_t saddr, const void* gptr) {
    asm volatile("cp.async.cg.shared.global [%0], [%1], 16;" :: "r"(saddr), "l"(gptr));
}
#define CP_COMMIT() asm volatile("cp.async.commit_group;" ::: "memory")

#define LDSM4(r, addr) \
    asm volatile("ldmatrix.sync.aligned.m8n8.x4.shared.b16 {%0,%1,%2,%3}, [%4];" \
        : "=r"((r)[0]), "=r"((r)[1]), "=r"((r)[2]), "=r"((r)[3]) : "r"(addr))

#define MMA16816(c, a, b0v, b1v) \
    asm volatile("mma.sync.aligned.m16n8k16.row.col.f32.bf16.bf16.f32 " \
        "{%0,%1,%2,%3}, {%4,%5,%6,%7}, {%8,%9}, {%0,%1,%2,%3};" \
        : "+f"((c)[0]), "+f"((c)[1]), "+f"((c)[2]), "+f"((c)[3]) \
        : "r"((a)[0]), "r"((a)[1]), "r"((a)[2]), "r"((a)[3]), "r"(b0v), "r"(b1v))

// ---------------------------------------------------------------------------
// bf16-split tensor-core GEMM (NT): C[m][n] = sum_k A[m][k]*B[n][k]
// C = Ahi*Bhi + Ahi*Blo + Alo*Bhi  (fp32 accum)
// 128x128 tile, BK=32, 256 threads (8 warps = 4m x 2n of 32x64), 4 cp.async stages.
// Smem rows padded to 80B -> conflict-free ldmatrix without XOR swizzle.
// ---------------------------------------------------------------------------
#define ROWB   80
#define TILEB  (128 * ROWB)        // 10240 B
#define STAGEB (4 * TILEB)         // 40960 B (Ahi,Alo,Bhi,Blo)
#define NSTG   4
#define GSMEM  (NSTG * STAGEB)     // 163840 B

__global__ __launch_bounds__(256, 1) void gemm_bf16x3(
    const __nv_bfloat16* __restrict__ Ahi, const __nv_bfloat16* __restrict__ Alo,
    const __nv_bfloat16* __restrict__ Bhi, const __nv_bfloat16* __restrict__ Blo,
    float* __restrict__ C, int M, int N, int K)
{
    extern __shared__ __align__(16) char smem_raw[];
    const uint32_t sbase = smem_to_u32(smem_raw);

    const int tid  = threadIdx.x;
    const int lane = tid & 31;
    const int warp = tid >> 5;
    const int wm   = warp & 3;          // 0..3  -> rows 32*wm
    const int wn   = warp >> 2;         // 0..1  -> cols 64*wn
    const int bm   = blockIdx.y * 128;
    const int bn   = blockIdx.x * 128;
    const int NT   = K / 32;

    const char* A0 = (const char*)(Ahi + (size_t)bm * K);
    const char* A1 = (const char*)(Alo + (size_t)bm * K);
    const char* B0 = (const char*)(Bhi + (size_t)bn * K);
    const char* B1 = (const char*)(Blo + (size_t)bn * K);

    // per-thread cooperative-load mapping: 512 chunks of 16B per tile
    const int lr  = tid >> 2;           // wait: 512 chunks over 256 threads -> 2 per tile
    (void)lr;

    // fragment-load base offsets (stage-relative, per tile)
    const uint32_t aOff = (uint32_t)((wm * 32 + (lane & 15)) * ROWB + (lane >> 4) * 16);
    const uint32_t bOff = (uint32_t)((wn * 64 + (lane & 7) + ((lane >> 4) & 1) * 8) * ROWB
                                     + ((lane >> 3) & 1) * 16);

    float acc[2][8][4];
#pragma unroll
    for (int mt = 0; mt < 2; ++mt)
#pragma unroll
        for (int nt = 0; nt < 8; ++nt)
#pragma unroll
            for (int e = 0; e < 4; ++e) acc[mt][nt][e] = 0.0f;

    // ---- stage loader: 4 tiles x 128 rows x 4 x 16B chunks ----
    auto load_stage = [&](int kt, int s) {
        const uint32_t st = sbase + (uint32_t)s * STAGEB;
        const size_t kbyte = (size_t)kt * 64;    // kt*32 bf16 * 2B
#pragma unroll
        for (int t = 0; t < 4; ++t) {
            const char* src = (t == 0) ? A0 : (t == 1) ? A1 : (t == 2) ? B0 : B1;
            const uint32_t tb = st + t * TILEB;
#pragma unroll
            for (int j = 0; j < 2; ++j) {
                int c  = tid + j * 256;          // 0..511
                int r  = c >> 2;                 // row 0..127
                int kb = (c & 3) * 16;           // 0,16,32,48
                cp16(tb + (uint32_t)(r * ROWB + kb),
                     src + (size_t)r * K * 2 + kbyte + kb);
            }
        }
        CP_COMMIT();
    };

    // prologue: prefetch 3 stages
    load_stage(0, 0);
    load_stage(1, 1);
    load_stage(2, 2);

    for (int kt = 0; kt < NT; ++kt) {
        const int s = kt & 3;
        const int issued = (kt + 3 < NT) ? (kt + 3) : NT;
        const int pend   = issued - kt - 1;      // 2,2,...,1,0
        if (pend >= 2)      asm volatile("cp.async.wait_group 2;" ::: "memory");
        else if (pend == 1) asm volatile("cp.async.wait_group 1;" ::: "memory");
        else                asm volatile("cp.async.wait_group 0;" ::: "memory");
        __syncthreads();

        if (kt + 3 < NT) load_stage(kt + 3, (kt + 3) & 3);

        const uint32_t st   = sbase + (uint32_t)s * STAGEB;
        const uint32_t stA0 = st;
        const uint32_t stA1 = st + TILEB;
        const uint32_t stB0 = st + 2 * TILEB;
        const uint32_t stB1 = st + 3 * TILEB;

#pragma unroll
        for (int ks = 0; ks < 2; ++ks) {
            uint32_t ah[2][4], al[2][4], bh[4][4], bl[4][4];
#pragma unroll
            for (int mt = 0; mt < 2; ++mt) {
                LDSM4(ah[mt], stA0 + aOff + mt * (16 * ROWB) + ks * 32);
                LDSM4(al[mt], stA1 + aOff + mt * (16 * ROWB) + ks * 32);
            }
#pragma unroll
            for (int np = 0; np < 4; ++np) {
                LDSM4(bh[np], stB0 + bOff + np * (16 * ROWB) + ks * 32);
                LDSM4(bl[np], stB1 + bOff + np * (16 * ROWB) + ks * 32);
            }
#pragma unroll
            for (int mt = 0; mt < 2; ++mt) {
#pragma unroll
                for (int np = 0; np < 4; ++np) {
                    MMA16816(acc[mt][2 * np],     ah[mt], bh[np][0], bh[np][1]);
                    MMA16816(acc[mt][2 * np + 1], ah[mt], bh[np][2], bh[np][3]);
                    MMA16816(acc[mt][2 * np],     ah[mt], bl[np][0], bl[np][1]);
                    MMA16816(acc[mt][2 * np + 1], ah[mt], bl[np][2], bl[np][3]);
                    MMA16816(acc[mt][2 * np],     al[mt], bh[np][0], bh[np][1]);
                    MMA16816(acc[mt][2 * np + 1], al[mt], bh[np][2], bh[np][3]);
                }
            }
        }
    }

    // epilogue: D fragment (row=lane/4, colpair=lane%4) direct stores
    const int rbase = bm + wm * 32 + (lane >> 2);
    const int cbase = bn + wn * 64 + (lane & 3) * 2;
#pragma unroll
    for (int mt = 0; mt < 2; ++mt) {
#pragma unroll
        for (int nt = 0; nt < 8; ++nt) {
            int grow = rbase + mt * 16;
            int gcol = cbase + nt * 8;
            *(float2*)(C + (size_t)grow * N + gcol) =
                make_float2(acc[mt][nt][0], acc[mt][nt][1]);
            *(float2*)(C + (size_t)(grow + 8) * N + gcol) =
                make_float2(acc[mt][nt][2], acc[mt][nt][3]);
        }
    }
}

// ---------------------------------------------------------------------------
// fp32 -> (bf16 hi, bf16 lo) split
// ---------------------------------------------------------------------------
__global__ void split_kernel(const float4* __restrict__ in,
                             __nv_bfloat162* __restrict__ hi,
                             __nv_bfloat162* __restrict__ lo, int n4)
{
    int i = blockIdx.x * blockDim.x + threadIdx.x;
    if (i >= n4) return;
    float4 v = in[i];
    __nv_bfloat16 h0 = __float2bfloat16(v.x);
    __nv_bfloat16 h1 = __float2bfloat16(v.y);
    __nv_bfloat16 h2 = __float2bfloat16(v.z);
    __nv_bfloat16 h3 = __float2bfloat16(v.w);
    __nv_bfloat16 l0 = __float2bfloat16(v.x - __bfloat162float(h0));
    __nv_bfloat16 l1 = __float2bfloat16(v.y - __bfloat162float(h1));
    __nv_bfloat16 l2 = __float2bfloat16(v.z - __bfloat162float(h2));
    __nv_bfloat16 l3 = __float2bfloat16(v.w - __bfloat162float(h3));
    hi[2 * i]     = __halves2bfloat162(h0, h1);
    hi[2 * i + 1] = __halves2bfloat162(h2, h3);
    lo[2 * i]     = __halves2bfloat162(l0, l1);
    lo[2 * i + 1] = __halves2bfloat162(l2, l3);
}

// ---------------------------------------------------------------------------
// Sliding-window attention (unchanged — 613us)
// ---------------------------------------------------------------------------
__global__ __launch_bounds__(128) void swa_kernel(
    const float* __restrict__ Q, const float* __restrict__ Kt,
    const float* __restrict__ Vt, float* __restrict__ O)
{
    const int i = blockIdx.x;
    const int h = blockIdx.y;
    const int b = blockIdx.z;
    const int r = threadIdx.x;

    __shared__ __align__(16) float Kc[64][64];
    __shared__ __align__(16) float Vc[64][64];

    const float scale = 0.125f;

    float q[DK];
    const size_t rowoff = ((size_t)b * T_ + (size_t)i * BS_ + r) * D_ + (size_t)h * DK;
#pragma unroll
    for (int d = 0; d < DK; d += 4) {
        float4 t = *(const float4*)(Q + rowoff + d);
        q[d] = t.x; q[d + 1] = t.y; q[d + 2] = t.z; q[d + 3] = t.w;
    }

    float o[DK];
#pragma unroll
    for (int d = 0; d < DK; ++d) o[d] = 0.0f;
    float mval = -INFINITY;
    float l = 0.0f;

    const int base_t  = (i - 1) * BS_;
    const int cmin    = (i == 0) ? 128 : r;
    const int cmax    = r + 128;
    const int c_start = (i == 0) ? 128 : 0;

    const int sub = r >> 4;
    const int d4  = (r & 15) * 4;

    for (int c0 = c_start; c0 < 256; c0 += 64) {
        __syncthreads();
#pragma unroll
        for (int it = 0; it < 8; ++it) {
            int j  = it * 8 + sub;
            int tk = base_t + c0 + j;
            size_t off = ((size_t)b * T_ + tk) * D_ + (size_t)h * DK + d4;
            float4 kv = *(const float4*)(Kt + off);
            float4 vv = *(const float4*)(Vt + off);
            *(float4*)&Kc[j][d4] = kv;
            *(float4*)&Vc[j][d4] = vv;
        }
        __syncthreads();

        for (int j = 0; j < 64; ++j) {
            const int c = c0 + j;
            if (c < cmin || c > cmax) continue;

            float s = 0.0f;
#pragma unroll
            for (int d = 0; d < DK; d += 4) {
                float4 k4 = *(const float4*)&Kc[j][d];
                s += q[d] * k4.x + q[d + 1] * k4.y + q[d + 2] * k4.z + q[d + 3] * k4.w;
            }
            s *= scale;

            if (s > mval) {
                float corr = __expf(mval - s);
                l *= corr;
#pragma unroll
                for (int d = 0; d < DK; ++d) o[d] *= corr;
                mval = s;
            }
            float p = __expf(s - mval);
            l += p;
#pragma unroll
            for (int d = 0; d < DK; d += 4) {
                float4 v4 = *(const float4*)&Vc[j][d];
                o[d]     += p * v4.x;
                o[d + 1] += p * v4.y;
                o[d + 2] += p * v4.z;
                o[d + 3] += p * v4.w;
            }
        }
    }

    const float inv = 1.0f / l;
    float* op = O + rowoff;
#pragma unroll
    for (int d = 0; d < DK; d += 4) {
        *(float4*)(op + d) = make_float4(o[d] * inv, o[d + 1] * inv,
                                         o[d + 2] * inv, o[d + 3] * inv);
    }
}

// ---------------------------------------------------------------------------
// Launch
// ---------------------------------------------------------------------------
extern "C" void kernel_launch(void* const* d_in, const int* in_sizes, int n_in,
                              void* d_out, int out_size)
{
    const float* x  = (const float*)d_in[0];
    const float* W[4] = { (const float*)d_in[1], (const float*)d_in[2],
                          (const float*)d_in[3], (const float*)d_in[4] };
    float* out = (float*)d_out;

    float *qp, *kp, *vp, *aop;
    cudaGetSymbolAddress((void**)&qp,  g_Q);
    cudaGetSymbolAddress((void**)&kp,  g_K);
    cudaGetSymbolAddress((void**)&vp,  g_V);
    cudaGetSymbolAddress((void**)&aop, g_AO);
    __nv_bfloat16 *xhi, *xlo, *aohi, *aolo, *whi, *wlo;
    cudaGetSymbolAddress((void**)&xhi,  g_xhi);
    cudaGetSymbolAddress((void**)&xlo,  g_xlo);
    cudaGetSymbolAddress((void**)&aohi, g_aohi);
    cudaGetSymbolAddress((void**)&aolo, g_aolo);
    cudaGetSymbolAddress((void**)&whi,  g_whi);
    cudaGetSymbolAddress((void**)&wlo,  g_wlo);

    cudaFuncSetAttribute(gemm_bf16x3, cudaFuncAttributeMaxDynamicSharedMemorySize, GSMEM);

    const int nX  = M_ * D_;
    const int nW  = D_ * D_;
    const int thr = 256;

    split_kernel<<<(nX / 4 + thr - 1) / thr, thr>>>(
        (const float4*)x, (__nv_bfloat162*)xhi, (__nv_bfloat162*)xlo, nX / 4);
    for (int w = 0; w < 4; ++w)
        split_kernel<<<(nW / 4 + thr - 1) / thr, thr>>>(
            (const float4*)W[w],
            (__nv_bfloat162*)(whi + (size_t)w * nW),
            (__nv_bfloat162*)(wlo + (size_t)w * nW), nW / 4);

    dim3 gg(D_ / 128, M_ / 128);        // (16, 64)
    gemm_bf16x3<<<gg, 256, GSMEM>>>(xhi, xlo, whi + 0 * (size_t)nW, wlo + 0 * (size_t)nW, qp, M_, D_, D_);
    gemm_bf16x3<<<gg, 256, GSMEM>>>(xhi, xlo, whi + 1 * (size_t)nW, wlo + 1 * (size_t)nW, kp, M_, D_, D_);
    gemm_bf16x3<<<gg, 256, GSMEM>>>(xhi, xlo, whi + 2 * (size_t)nW, wlo + 2 * (size_t)nW, vp, M_, D_, D_);

    dim3 ga(NB, H_, B_);
    swa_kernel<<<ga, 128>>>(qp, kp, vp, aop);

    split_kernel<<<(nX / 4 + thr - 1) / thr, thr>>>(
        (const float4*)aop, (__nv_bfloat162*)aohi, (__nv_bfloat162*)aolo, nX / 4);
    gemm_bf16x3<<<gg, 256, GSMEM>>>(aohi, aolo, whi + 3 * (size_t)nW, wlo + 3 * (size_t)nW, out, M_, D_, D_);
}

// round 4
// speedup vs baseline: 2.2224x; 1.1265x over previous
#include <cuda_runtime.h>
#include <cuda_bf16.h>
#include <math.h>
#include <stdint.h>

// Problem dims (fixed)
#define B_   2
#define T_   4096
#define D_   2048
#define H_   32
#define DK   64
#define BS_  128
#define NB   (T_ / BS_)     // 32
#define M_   (B_ * T_)      // 8192

// ---------------------------------------------------------------------------
// Scratch device globals
// ---------------------------------------------------------------------------
__device__ float g_Q [(size_t)M_ * D_];
__device__ float g_K [(size_t)M_ * D_];
__device__ float g_V [(size_t)M_ * D_];

__device__ __nv_bfloat16 g_xhi[(size_t)M_ * D_];
__device__ __nv_bfloat16 g_xlo[(size_t)M_ * D_];
__device__ __nv_bfloat16 g_aohi[(size_t)M_ * D_];
__device__ __nv_bfloat16 g_aolo[(size_t)M_ * D_];
__device__ __nv_bfloat16 g_whi[4][(size_t)D_ * D_];
__device__ __nv_bfloat16 g_wlo[4][(size_t)D_ * D_];

// ---------------------------------------------------------------------------
// helpers
// ---------------------------------------------------------------------------
__device__ __forceinline__ uint32_t smem_to_u32(const void* p) {
    uint32_t a;
    asm("{ .reg .u64 t; cvta.to.shared.u64 t, %1; cvt.u32.u64 %0, t; }" : "=r"(a) : "l"(p));
    return a;
}
__device__ __forceinline__ void cp16(uint32_t saddr, const void* gptr) {
    asm volatile("cp.async.cg.shared.global [%0], [%1], 16;" :: "r"(saddr), "l"(gptr));
}
#define CP_COMMIT() asm volatile("cp.async.commit_group;" ::: "memory")

#define LDSM4(r, addr) \
    asm volatile("ldmatrix.sync.aligned.m8n8.x4.shared.b16 {%0,%1,%2,%3}, [%4];" \
        : "=r"((r)[0]), "=r"((r)[1]), "=r"((r)[2]), "=r"((r)[3]) : "r"(addr))

#define MMA16816(c, a, b0v, b1v) \
    asm volatile("mma.sync.aligned.m16n8k16.row.col.f32.bf16.bf16.f32 " \
        "{%0,%1,%2,%3}, {%4,%5,%6,%7}, {%8,%9}, {%0,%1,%2,%3};" \
        : "+f"((c)[0]), "+f"((c)[1]), "+f"((c)[2]), "+f"((c)[3]) \
        : "r"((a)[0]), "r"((a)[1]), "r"((a)[2]), "r"((a)[3]), "r"(b0v), "r"(b1v))

// ---------------------------------------------------------------------------
// bf16-split tensor-core GEMM (NT): C = Ahi*Bhi + Ahi*Blo + Alo*Bhi (fp32 acc)
// 128x128 tile, BK=64, 256 threads (8 warps = 4m x 2n of 32x64), 3 stages,
// register double-buffered fragments. ROWB=144 pad: banks (36r)%32 distinct.
// ---------------------------------------------------------------------------
#define ROWB   144
#define TILEB  (128 * ROWB)        // 18432 B
#define STAGEB (4 * TILEB)         // 73728 B
#define NSTG   3
#define GSMEM  (NSTG * STAGEB)     // 221184 B

__global__ __launch_bounds__(256, 1) void gemm_bf16x3(
    const __nv_bfloat16* __restrict__ Ahi, const __nv_bfloat16* __restrict__ Alo,
    const __nv_bfloat16* __restrict__ Bhi, const __nv_bfloat16* __restrict__ Blo,
    float* __restrict__ C, int M, int N, int K)
{
    extern __shared__ __align__(16) char smem_raw[];
    const uint32_t sbase = smem_to_u32(smem_raw);

    const int tid  = threadIdx.x;
    const int lane = tid & 31;
    const int warp = tid >> 5;
    const int wm   = warp & 3;
    const int wn   = warp >> 2;
    const int bm   = blockIdx.y * 128;
    const int bn   = blockIdx.x * 128;
    const int NT   = K / 64;

    const char* A0 = (const char*)(Ahi + (size_t)bm * K);
    const char* A1 = (const char*)(Alo + (size_t)bm * K);
    const char* B0 = (const char*)(Bhi + (size_t)bn * K);
    const char* B1 = (const char*)(Blo + (size_t)bn * K);

    const uint32_t aOff = (uint32_t)((wm * 32 + (lane & 15)) * ROWB + (lane >> 4) * 16);
    const uint32_t bOff = (uint32_t)((wn * 64 + (lane & 7) + ((lane >> 4) & 1) * 8) * ROWB
                                     + ((lane >> 3) & 1) * 16);

    float acc[2][8][4];
#pragma unroll
    for (int mt = 0; mt < 2; ++mt)
#pragma unroll
        for (int nt = 0; nt < 8; ++nt)
#pragma unroll
            for (int e = 0; e < 4; ++e) acc[mt][nt][e] = 0.0f;

    // stage loader: 4 tiles x 128 rows x 8 x 16B chunks = 1024 chunks, 4/thread
    auto load_stage = [&](int kt, int s) {
        const uint32_t st = sbase + (uint32_t)s * STAGEB;
        const size_t kbyte = (size_t)kt * 128;   // kt*64 bf16 * 2B
#pragma unroll
        for (int t = 0; t < 4; ++t) {
            const char* src = (t == 0) ? A0 : (t == 1) ? A1 : (t == 2) ? B0 : B1;
            const uint32_t tb = st + t * TILEB;
#pragma unroll
            for (int j = 0; j < 4; ++j) {
                int c  = tid + j * 256;          // 0..1023
                int r  = c >> 3;                 // row 0..127
                int kb = (c & 7) * 16;           // 0..112
                cp16(tb + (uint32_t)(r * ROWB + kb),
                     src + (size_t)r * K * 2 + kbyte + kb);
            }
        }
        CP_COMMIT();
    };

    load_stage(0, 0);
    load_stage(1, 1);
    load_stage(2, 2);

#define LDFRAGS(buf, ks) do { \
    _Pragma("unroll") \
    for (int _mt = 0; _mt < 2; ++_mt) { \
        LDSM4(ah[buf][_mt], stA0 + aOff + _mt * (16 * ROWB) + (ks) * 32); \
        LDSM4(al[buf][_mt], stA1 + aOff + _mt * (16 * ROWB) + (ks) * 32); } \
    _Pragma("unroll") \
    for (int _np = 0; _np < 4; ++_np) { \
        LDSM4(bh[buf][_np], stB0 + bOff + _np * (16 * ROWB) + (ks) * 32); \
        LDSM4(bl[buf][_np], stB1 + bOff + _np * (16 * ROWB) + (ks) * 32); } \
} while (0)

    for (int kt = 0; kt < NT; ++kt) {
        const int issued = (kt + 3 < NT) ? (kt + 3) : NT;
        const int pend   = issued - kt - 1;
        if (pend >= 2)      asm volatile("cp.async.wait_group 2;" ::: "memory");
        else if (pend == 1) asm volatile("cp.async.wait_group 1;" ::: "memory");
        else                asm volatile("cp.async.wait_group 0;" ::: "memory");
        __syncthreads();

        const uint32_t st   = sbase + (uint32_t)(kt % 3) * STAGEB;
        const uint32_t stA0 = st;
        const uint32_t stA1 = st + TILEB;
        const uint32_t stB0 = st + 2 * TILEB;
        const uint32_t stB1 = st + 3 * TILEB;

        uint32_t ah[2][2][4], al[2][2][4], bh[2][4][4], bl[2][4][4];
        LDFRAGS(0, 0);

#pragma unroll
        for (int ks = 0; ks < 4; ++ks) {
            const int cur = ks & 1;
            const int nxt = cur ^ 1;
            if (ks < 3) {
                switch (ks + 1) {                 // keep immediate offsets
                    case 1: LDFRAGS(nxt, 1); break;
                    case 2: LDFRAGS(nxt, 2); break;
                    default: LDFRAGS(nxt, 3); break;
                }
            }
#pragma unroll
            for (int mt = 0; mt < 2; ++mt) {
#pragma unroll
                for (int np = 0; np < 4; ++np) {
                    MMA16816(acc[mt][2 * np],     ah[cur][mt], bh[cur][np][0], bh[cur][np][1]);
                    MMA16816(acc[mt][2 * np + 1], ah[cur][mt], bh[cur][np][2], bh[cur][np][3]);
                    MMA16816(acc[mt][2 * np],     ah[cur][mt], bl[cur][np][0], bl[cur][np][1]);
                    MMA16816(acc[mt][2 * np + 1], ah[cur][mt], bl[cur][np][2], bl[cur][np][3]);
                    MMA16816(acc[mt][2 * np],     al[cur][mt], bh[cur][np][0], bh[cur][np][1]);
                    MMA16816(acc[mt][2 * np + 1], al[cur][mt], bh[cur][np][2], bh[cur][np][3]);
                }
            }
        }

        __syncthreads();                          // all warps done reading stage kt
        if (kt + 3 < NT) load_stage(kt + 3, kt % 3);
    }

    const int rbase = bm + wm * 32 + (lane >> 2);
    const int cbase = bn + wn * 64 + (lane & 3) * 2;
#pragma unroll
    for (int mt = 0; mt < 2; ++mt) {
#pragma unroll
        for (int nt = 0; nt < 8; ++nt) {
            int grow = rbase + mt * 16;
            int gcol = cbase + nt * 8;
            *(float2*)(C + (size_t)grow * N + gcol) =
                make_float2(acc[mt][nt][0], acc[mt][nt][1]);
            *(float2*)(C + (size_t)(grow + 8) * N + gcol) =
                make_float2(acc[mt][nt][2], acc[mt][nt][3]);
        }
    }
#undef LDFRAGS
}

// ---------------------------------------------------------------------------
// fp32 -> (bf16 hi, bf16 lo) splits
// ---------------------------------------------------------------------------
__global__ void split_kernel(const float4* __restrict__ in,
                             __nv_bfloat162* __restrict__ hi,
                             __nv_bfloat162* __restrict__ lo, int n4)
{
    int i = blockIdx.x * blockDim.x + threadIdx.x;
    if (i >= n4) return;
    float4 v = in[i];
    __nv_bfloat16 h0 = __float2bfloat16(v.x);
    __nv_bfloat16 h1 = __float2bfloat16(v.y);
    __nv_bfloat16 h2 = __float2bfloat16(v.z);
    __nv_bfloat16 h3 = __float2bfloat16(v.w);
    __nv_bfloat16 l0 = __float2bfloat16(v.x - __bfloat162float(h0));
    __nv_bfloat16 l1 = __float2bfloat16(v.y - __bfloat162float(h1));
    __nv_bfloat16 l2 = __float2bfloat16(v.z - __bfloat162float(h2));
    __nv_bfloat16 l3 = __float2bfloat16(v.w - __bfloat162float(h3));
    hi[2 * i]     = __halves2bfloat162(h0, h1);
    hi[2 * i + 1] = __halves2bfloat162(h2, h3);
    lo[2 * i]     = __halves2bfloat162(l0, l1);
    lo[2 * i + 1] = __halves2bfloat162(l2, l3);
}

struct WPtrs { const float4* w[4]; };

__global__ void split_w_kernel(WPtrs wp, __nv_bfloat162* __restrict__ hi,
                               __nv_bfloat162* __restrict__ lo, int n4)
{
    int i = blockIdx.x * blockDim.x + threadIdx.x;
    if (i >= n4) return;
    int w = blockIdx.y;
    const float4* in = wp.w[w];
    size_t off = (size_t)w * n4;
    float4 v = in[i];
    __nv_bfloat16 h0 = __float2bfloat16(v.x);
    __nv_bfloat16 h1 = __float2bfloat16(v.y);
    __nv_bfloat16 h2 = __float2bfloat16(v.z);
    __nv_bfloat16 h3 = __float2bfloat16(v.w);
    __nv_bfloat16 l0 = __float2bfloat16(v.x - __bfloat162float(h0));
    __nv_bfloat16 l1 = __float2bfloat16(v.y - __bfloat162float(h1));
    __nv_bfloat16 l2 = __float2bfloat16(v.z - __bfloat162float(h2));
    __nv_bfloat16 l3 = __float2bfloat16(v.w - __bfloat162float(h3));
    hi[2 * (off + i)]     = __halves2bfloat162(h0, h1);
    hi[2 * (off + i) + 1] = __halves2bfloat162(h2, h3);
    lo[2 * (off + i)]     = __halves2bfloat162(l0, l1);
    lo[2 * (off + i) + 1] = __halves2bfloat162(l2, l3);
}

// ---------------------------------------------------------------------------
// Sliding-window attention; writes bf16 hi/lo directly (feeds final GEMM).
// ---------------------------------------------------------------------------
__global__ __launch_bounds__(128) void swa_kernel(
    const float* __restrict__ Q, const float* __restrict__ Kt,
    const float* __restrict__ Vt,
    __nv_bfloat16* __restrict__ Ohi, __nv_bfloat16* __restrict__ Olo)
{
    const int i = blockIdx.x;
    const int h = blockIdx.y;
    const int b = blockIdx.z;
    const int r = threadIdx.x;

    __shared__ __align__(16) float Kc[64][64];
    __shared__ __align__(16) float Vc[64][64];

    const float scale = 0.125f;

    float q[DK];
    const size_t rowoff = ((size_t)b * T_ + (size_t)i * BS_ + r) * D_ + (size_t)h * DK;
#pragma unroll
    for (int d = 0; d < DK; d += 4) {
        float4 t = *(const float4*)(Q + rowoff + d);
        q[d] = t.x; q[d + 1] = t.y; q[d + 2] = t.z; q[d + 3] = t.w;
    }

    float o[DK];
#pragma unroll
    for (int d = 0; d < DK; ++d) o[d] = 0.0f;
    float mval = -INFINITY;
    float l = 0.0f;

    const int base_t  = (i - 1) * BS_;
    const int cmin    = (i == 0) ? 128 : r;
    const int cmax    = r + 128;
    const int c_start = (i == 0) ? 128 : 0;

    const int sub = r >> 4;
    const int d4  = (r & 15) * 4;

    for (int c0 = c_start; c0 < 256; c0 += 64) {
        __syncthreads();
#pragma unroll
        for (int it = 0; it < 8; ++it) {
            int j  = it * 8 + sub;
            int tk = base_t + c0 + j;
            size_t off = ((size_t)b * T_ + tk) * D_ + (size_t)h * DK + d4;
            float4 kv = *(const float4*)(Kt + off);
            float4 vv = *(const float4*)(Vt + off);
            *(float4*)&Kc[j][d4] = kv;
            *(float4*)&Vc[j][d4] = vv;
        }
        __syncthreads();

        for (int j = 0; j < 64; ++j) {
            const int c = c0 + j;
            if (c < cmin || c > cmax) continue;

            float s0 = 0.0f, s1 = 0.0f;     // dual accumulators: shorter chain
#pragma unroll
            for (int d = 0; d < 32; d += 4) {
                float4 k4 = *(const float4*)&Kc[j][d];
                s0 += q[d] * k4.x + q[d + 1] * k4.y + q[d + 2] * k4.z + q[d + 3] * k4.w;
            }
#pragma unroll
            for (int d = 32; d < 64; d += 4) {
                float4 k4 = *(const float4*)&Kc[j][d];
                s1 += q[d] * k4.x + q[d + 1] * k4.y + q[d + 2] * k4.z + q[d + 3] * k4.w;
            }
            float s = (s0 + s1) * scale;

            if (s > mval) {
                float corr = __expf(mval - s);
                l *= corr;
#pragma unroll
                for (int d = 0; d < DK; ++d) o[d] *= corr;
                mval = s;
            }
            float p = __expf(s - mval);
            l += p;
#pragma unroll
            for (int d = 0; d < DK; d += 4) {
                float4 v4 = *(const float4*)&Vc[j][d];
                o[d]     += p * v4.x;
                o[d + 1] += p * v4.y;
                o[d + 2] += p * v4.z;
                o[d + 3] += p * v4.w;
            }
        }
    }

    const float inv = 1.0f / l;
    __nv_bfloat162* hp = (__nv_bfloat162*)(Ohi + rowoff);
    __nv_bfloat162* lp = (__nv_bfloat162*)(Olo + rowoff);
#pragma unroll
    for (int d = 0; d < DK; d += 2) {
        float a0 = o[d] * inv, a1 = o[d + 1] * inv;
        __nv_bfloat16 h0 = __float2bfloat16(a0);
        __nv_bfloat16 h1 = __float2bfloat16(a1);
        __nv_bfloat16 l0 = __float2bfloat16(a0 - __bfloat162float(h0));
        __nv_bfloat16 l1 = __float2bfloat16(a1 - __bfloat162float(h1));
        hp[d >> 1] = __halves2bfloat162(h0, h1);
        lp[d >> 1] = __halves2bfloat162(l0, l1);
    }
}

// ---------------------------------------------------------------------------
// Launch
// ---------------------------------------------------------------------------
extern "C" void kernel_launch(void* const* d_in, const int* in_sizes, int n_in,
                              void* d_out, int out_size)
{
    const float* x  = (const float*)d_in[0];
    float* out = (float*)d_out;

    float *qp, *kp, *vp;
    cudaGetSymbolAddress((void**)&qp,  g_Q);
    cudaGetSymbolAddress((void**)&kp,  g_K);
    cudaGetSymbolAddress((void**)&vp,  g_V);
    __nv_bfloat16 *xhi, *xlo, *aohi, *aolo, *whi, *wlo;
    cudaGetSymbolAddress((void**)&xhi,  g_xhi);
    cudaGetSymbolAddress((void**)&xlo,  g_xlo);
    cudaGetSymbolAddress((void**)&aohi, g_aohi);
    cudaGetSymbolAddress((void**)&aolo, g_aolo);
    cudaGetSymbolAddress((void**)&whi,  g_whi);
    cudaGetSymbolAddress((void**)&wlo,  g_wlo);

    cudaFuncSetAttribute(gemm_bf16x3, cudaFuncAttributeMaxDynamicSharedMemorySize, GSMEM);

    const int nX  = M_ * D_;
    const int nW  = D_ * D_;
    const int thr = 256;

    split_kernel<<<(nX / 4 + thr - 1) / thr, thr>>>(
        (const float4*)x, (__nv_bfloat162*)xhi, (__nv_bfloat162*)xlo, nX / 4);

    WPtrs wp;
    wp.w[0] = (const float4*)d_in[1];
    wp.w[1] = (const float4*)d_in[2];
    wp.w[2] = (const float4*)d_in[3];
    wp.w[3] = (const float4*)d_in[4];
    dim3 gw((nW / 4 + thr - 1) / thr, 4);
    split_w_kernel<<<gw, thr>>>(wp, (__nv_bfloat162*)whi, (__nv_bfloat162*)wlo, nW / 4);

    dim3 gg(D_ / 128, M_ / 128);        // (16, 64)
    gemm_bf16x3<<<gg, 256, GSMEM>>>(xhi, xlo, whi + 0 * (size_t)nW, wlo + 0 * (size_t)nW, qp, M_, D_, D_);
    gemm_bf16x3<<<gg, 256, GSMEM>>>(xhi, xlo, whi + 1 * (size_t)nW, wlo + 1 * (size_t)nW, kp, M_, D_, D_);
    gemm_bf16x3<<<gg, 256, GSMEM>>>(xhi, xlo, whi + 2 * (size_t)nW, wlo + 2 * (size_t)nW, vp, M_, D_, D_);

    dim3 ga(NB, H_, B_);
    swa_kernel<<<ga, 128>>>(qp, kp, vp, aohi, aolo);

    gemm_bf16x3<<<gg, 256, GSMEM>>>(aohi, aolo, whi + 3 * (size_t)nW, wlo + 3 * (size_t)nW, out, M_, D_, D_);
}